// round 1
// baseline (speedup 1.0000x reference)
#include <cuda_runtime.h>
#include <float.h>
#include <math.h>

#define NB 32
#define NL 2048
#define NC 1024
#define KSEL 20
#define GNEPS 1e-5f
#define NLT 16   // number of 128-row L tiles per batch

// ---------------- scratch (device globals; no allocations allowed) ----------
__device__ float g_pmax[NLT * NB * NC];
__device__ float g_psum[NLT * NB * NC];
__device__ float g_xA[NB * NC];
__device__ float g_xmean[NB * NC];
__device__ float g_tM[NB * NC];
__device__ float g_tA[NB * NC];
__device__ float g_gn1[NB * NC];
__device__ float g_gn2[NB * NC];
__device__ float g_v[NB * NC];
__device__ float g_u[NB * NC];
__device__ float g_s[NB * NL];
__device__ int   g_top[NB * KSEL];
__device__ float g_xg[NB * KSEL * NC];
__device__ float g_y[NB * KSEL * NC];

// ---------------------------------------------------------------------------
// GEMM1: x[b,l,d] = sum_c x0[b,l,c]*W[d,c] + bias[d], fused column max & sum
// over the 128 l-rows of this tile. Writes per-(ltile) partials (deterministic,
// no atomics). 128x128x8 tiling, 8x8 per thread, 256 threads.
// ---------------------------------------------------------------------------
__global__ void __launch_bounds__(256, 2)
gemm1_maxsum(const float* __restrict__ X0, const float* __restrict__ W,
             const float* __restrict__ bias)
{
    const int ltile = blockIdx.x;   // 0..15
    const int dtile = blockIdx.y;   // 0..7
    const int b     = blockIdx.z;   // 0..31

    const float* Aptr = X0 + ((size_t)b * NL + (size_t)ltile * 128) * NC;
    const float* Bptr = W + (size_t)dtile * 128 * NC;

    __shared__ float As[8][128];
    __shared__ float Bs[8][128];
    __shared__ float sred[16][128];

    const int tid  = threadIdx.x;
    const int tx   = tid & 15;
    const int ty   = tid >> 4;
    const int lrow = tid >> 1;        // 0..127
    const int lk4  = (tid & 1) * 4;   // 0 or 4

    float acc[8][8];
#pragma unroll
    for (int i = 0; i < 8; i++)
#pragma unroll
        for (int j = 0; j < 8; j++) acc[i][j] = 0.f;

    float4 a4 = *(const float4*)(Aptr + (size_t)lrow * NC + lk4);
    float4 b4 = *(const float4*)(Bptr + (size_t)lrow * NC + lk4);

    for (int k0 = 0; k0 < NC; k0 += 8) {
        __syncthreads();
        As[lk4 + 0][lrow] = a4.x; As[lk4 + 1][lrow] = a4.y;
        As[lk4 + 2][lrow] = a4.z; As[lk4 + 3][lrow] = a4.w;
        Bs[lk4 + 0][lrow] = b4.x; Bs[lk4 + 1][lrow] = b4.y;
        Bs[lk4 + 2][lrow] = b4.z; Bs[lk4 + 3][lrow] = b4.w;
        __syncthreads();
        if (k0 + 8 < NC) {
            a4 = *(const float4*)(Aptr + (size_t)lrow * NC + k0 + 8 + lk4);
            b4 = *(const float4*)(Bptr + (size_t)lrow * NC + k0 + 8 + lk4);
        }
#pragma unroll
        for (int kk = 0; kk < 8; kk++) {
            float ra[8], rb[8];
            *(float4*)(ra)     = *(const float4*)(&As[kk][ty * 8]);
            *(float4*)(ra + 4) = *(const float4*)(&As[kk][ty * 8 + 4]);
            *(float4*)(rb)     = *(const float4*)(&Bs[kk][tx * 8]);
            *(float4*)(rb + 4) = *(const float4*)(&Bs[kk][tx * 8 + 4]);
#pragma unroll
            for (int i = 0; i < 8; i++)
#pragma unroll
                for (int j = 0; j < 8; j++)
                    acc[i][j] += ra[i] * rb[j];
        }
    }

    // Epilogue: add bias, reduce max & sum over the tile's 128 rows per column.
    float cmax[8], csum[8];
#pragma unroll
    for (int j = 0; j < 8; j++) {
        float bd = __ldg(bias + dtile * 128 + tx * 8 + j);
        float m = -FLT_MAX, s = 0.f;
#pragma unroll
        for (int i = 0; i < 8; i++) {
            float v = acc[i][j] + bd;
            m = fmaxf(m, v);
            s += v;
        }
        cmax[j] = m; csum[j] = s;
    }
#pragma unroll
    for (int j = 0; j < 8; j++) sred[ty][tx * 8 + j] = cmax[j];
    __syncthreads();
    float rm = -FLT_MAX;
    if (tid < 128) {
#pragma unroll
        for (int t = 0; t < 16; t++) rm = fmaxf(rm, sred[t][tid]);
    }
    __syncthreads();
#pragma unroll
    for (int j = 0; j < 8; j++) sred[ty][tx * 8 + j] = csum[j];
    __syncthreads();
    if (tid < 128) {
        float rs = 0.f;
#pragma unroll
        for (int t = 0; t < 16; t++) rs += sred[t][tid];
        size_t o = ((size_t)ltile * NB + b) * NC + dtile * 128 + tid;
        g_pmax[o] = rm;
        g_psum[o] = rs;
    }
}

// Reduce the 16 per-tile partials -> x_A (max) and x_mean (mean over L).
__global__ void reduce_maxsum()
{
    int idx = blockIdx.x * 256 + threadIdx.x;   // 0 .. NB*NC-1
    float m = -FLT_MAX, s = 0.f;
#pragma unroll
    for (int t = 0; t < NLT; t++) {
        m = fmaxf(m, g_pmax[(size_t)t * NB * NC + idx]);
        s += g_psum[(size_t)t * NB * NC + idx];
    }
    g_xA[idx] = m;
    g_xmean[idx] = s * (1.0f / NL);
}

// out[b,n] = sum_k A[b,k]*M[n,k] + bias[n]   (M row-major [N,K]); warp per (b,n)
__global__ void __launch_bounds__(256)
small_gemm_T(const float* __restrict__ Ain, const float* __restrict__ M,
             const float* __restrict__ bias, float* __restrict__ out)
{
    int b = blockIdx.y;
    __shared__ float sA[NC];
    int tid = threadIdx.x;
    for (int i = tid; i < NC; i += 256) sA[i] = Ain[b * NC + i];
    __syncthreads();
    int warp = tid >> 5, lane = tid & 31;
    int n = blockIdx.x * 8 + warp;
    const float4* Mr = (const float4*)(M + (size_t)n * NC);
    const float4* Ar = (const float4*)sA;
    float acc = 0.f;
#pragma unroll 4
    for (int i = lane; i < NC / 4; i += 32) {
        float4 m4 = __ldg(&Mr[i]);
        float4 a4 = Ar[i];
        acc += m4.x * a4.x + m4.y * a4.y + m4.z * a4.z + m4.w * a4.w;
    }
#pragma unroll
    for (int o = 16; o; o >>= 1) acc += __shfl_xor_sync(0xffffffffu, acc, o);
    if (lane == 0) out[b * NC + n] = acc + __ldg(bias + n);
}

// GroupNorm on [NB, NC] rows, 32 groups of 32 channels (group == one warp).
__global__ void gn_kernel(const float* __restrict__ t, const float* __restrict__ w,
                          const float* __restrict__ bb, float* __restrict__ o)
{
    int b = blockIdx.x;
    int c = threadIdx.x;  // 1024 threads
    float v = t[b * NC + c];
    float s = v;
#pragma unroll
    for (int off = 16; off; off >>= 1) s += __shfl_xor_sync(0xffffffffu, s, off);
    float mean = s * (1.f / 32.f);
    float d = v - mean;
    float q = d * d;
#pragma unroll
    for (int off = 16; off; off >>= 1) q += __shfl_xor_sync(0xffffffffu, q, off);
    float var = q * (1.f / 32.f);
    o[b * NC + c] = d * rsqrtf(var + GNEPS) * __ldg(w + c) + __ldg(bb + c);
}

// out[b,c] (+)= sum_d A[b,d]*M[d,c]   (M row-major [D,C], reduce over rows)
template <bool ACCUM>
__global__ void __launch_bounds__(256)
small_gemm_N(const float* __restrict__ Ain, const float* __restrict__ M,
             float* __restrict__ out)
{
    int b = blockIdx.y;
    int c = blockIdx.x * 256 + threadIdx.x;
    __shared__ float sA[NC];
    for (int i = threadIdx.x; i < NC; i += 256) sA[i] = Ain[b * NC + i];
    __syncthreads();
    float acc = ACCUM ? out[b * NC + c] : 0.f;
#pragma unroll 8
    for (int d = 0; d < NC; d++)
        acc += sA[d] * __ldg(M + (size_t)d * NC + c);
    out[b * NC + c] = acc;
}

// s[b,l] = x0[b,l,:] . u[b,:]   (one warp per row, u staged in smem)
__global__ void __launch_bounds__(256)
dot_kernel(const float* __restrict__ X0)
{
    int b = blockIdx.y;
    __shared__ float su[NC];
    for (int i = threadIdx.x; i < NC; i += 256) su[i] = g_u[b * NC + i];
    __syncthreads();
    int warp = threadIdx.x >> 5, lane = threadIdx.x & 31;
    int l = blockIdx.x * 8 + warp;
    const float4* xr = (const float4*)(X0 + ((size_t)b * NL + l) * NC);
    const float4* ur = (const float4*)su;
    float acc = 0.f;
#pragma unroll 4
    for (int i = lane; i < NC / 4; i += 32) {
        float4 x = __ldg(&xr[i]);
        float4 u = ur[i];
        acc += x.x * u.x + x.y * u.y + x.z * u.z + x.w * u.w;
    }
#pragma unroll
    for (int o = 16; o; o >>= 1) acc += __shfl_xor_sync(0xffffffffu, acc, o);
    if (lane == 0) g_s[b * NL + l] = acc;
}

// Iterative top-20 per batch (ties -> lowest index, matching jax top_k).
__global__ void __launch_bounds__(256) topk_kernel()
{
    int b = blockIdx.x;
    __shared__ float vals[NL];
    __shared__ float rmx[256];
    __shared__ int   rix[256];
    int tid = threadIdx.x;
    for (int i = tid; i < NL; i += 256) vals[i] = g_s[b * NL + i];
    __syncthreads();
    for (int it = 0; it < KSEL; it++) {
        float m = -FLT_MAX; int mi = 0;
        for (int i = tid; i < NL; i += 256) {
            float v = vals[i];
            if (v > m) { m = v; mi = i; }
        }
        rmx[tid] = m; rix[tid] = mi;
        __syncthreads();
        for (int st = 128; st > 0; st >>= 1) {
            if (tid < st) {
                float vo = rmx[tid + st]; int io = rix[tid + st];
                if (vo > rmx[tid] || (vo == rmx[tid] && io < rix[tid])) {
                    rmx[tid] = vo; rix[tid] = io;
                }
            }
            __syncthreads();
        }
        if (tid == 0) {
            g_top[b * KSEL + it] = rix[0];
            vals[rix[0]] = -FLT_MAX;
        }
        __syncthreads();
    }
}

// Gather the 640 selected x0 rows.
__global__ void gather_kernel(const float* __restrict__ X0)
{
    int r = blockIdx.x;          // 0..639
    int b = r / KSEL;
    int l = g_top[r];
    const float4* src = (const float4*)(X0 + ((size_t)b * NL + l) * NC);
    float4* dst = (float4*)(g_xg + (size_t)r * NC);
    dst[threadIdx.x] = src[threadIdx.x];   // 256 threads * float4
}

// out[m,n] = sum_k A[m,k]*Bw[n,k] + bias[n]; M=640, N=K=1024. 64x64x16 tiles.
__global__ void __launch_bounds__(256)
gemm2(const float* __restrict__ A, const float* __restrict__ Bw,
      const float* __restrict__ bias, float* __restrict__ out)
{
    const int mtile = blockIdx.x, ntile = blockIdx.y;
    __shared__ float As[16][64];
    __shared__ float Bs[16][64];
    int tid = threadIdx.x;
    int tx = tid & 15, ty = tid >> 4;
    const float* Ap = A + (size_t)mtile * 64 * NC;
    const float* Bp = Bw + (size_t)ntile * 64 * NC;
    int lrow = tid >> 2;          // 0..63
    int lk4  = (tid & 3) * 4;     // 0,4,8,12

    float acc[4][4];
#pragma unroll
    for (int i = 0; i < 4; i++)
#pragma unroll
        for (int j = 0; j < 4; j++) acc[i][j] = 0.f;

    float4 a4 = *(const float4*)(Ap + (size_t)lrow * NC + lk4);
    float4 b4 = *(const float4*)(Bp + (size_t)lrow * NC + lk4);

    for (int k0 = 0; k0 < NC; k0 += 16) {
        __syncthreads();
        As[lk4 + 0][lrow] = a4.x; As[lk4 + 1][lrow] = a4.y;
        As[lk4 + 2][lrow] = a4.z; As[lk4 + 3][lrow] = a4.w;
        Bs[lk4 + 0][lrow] = b4.x; Bs[lk4 + 1][lrow] = b4.y;
        Bs[lk4 + 2][lrow] = b4.z; Bs[lk4 + 3][lrow] = b4.w;
        __syncthreads();
        if (k0 + 16 < NC) {
            a4 = *(const float4*)(Ap + (size_t)lrow * NC + k0 + 16 + lk4);
            b4 = *(const float4*)(Bp + (size_t)lrow * NC + k0 + 16 + lk4);
        }
#pragma unroll
        for (int kk = 0; kk < 16; kk++) {
            float ra[4], rb[4];
            *(float4*)ra = *(const float4*)(&As[kk][ty * 4]);
            *(float4*)rb = *(const float4*)(&Bs[kk][tx * 4]);
#pragma unroll
            for (int i = 0; i < 4; i++)
#pragma unroll
                for (int j = 0; j < 4; j++)
                    acc[i][j] += ra[i] * rb[j];
        }
    }
#pragma unroll
    for (int j = 0; j < 4; j++) {
        float bd = __ldg(bias + ntile * 64 + tx * 4 + j);
#pragma unroll
        for (int i = 0; i < 4; i++)
            out[((size_t)mtile * 64 + ty * 4 + i) * NC + ntile * 64 + tx * 4 + j] =
                acc[i][j] + bd;
    }
}

// ---------------------------------------------------------------------------
static float* symf(const void* symbol)
{
    void* p = nullptr;
    cudaGetSymbolAddress(&p, symbol);
    return (float*)p;
}

extern "C" void kernel_launch(void* const* d_in, const int* in_sizes, int n_in,
                              void* d_out, int out_size)
{
    const float* x0  = (const float*)d_in[0];
    const float* W   = (const float*)d_in[1];
    const float* b   = (const float*)d_in[2];
    const float* W1  = (const float*)d_in[3];
    const float* b1  = (const float*)d_in[4];
    const float* Wm  = (const float*)d_in[5];
    const float* bm  = (const float*)d_in[6];
    const float* Wa  = (const float*)d_in[7];
    const float* ba  = (const float*)d_in[8];
    const float* g1w = (const float*)d_in[9];
    const float* g1b = (const float*)d_in[10];
    const float* g2w = (const float*)d_in[11];
    const float* g2b = (const float*)d_in[12];
    float* out = (float*)d_out;

    float* p_xmean = symf(g_xmean);
    float* p_xA    = symf(g_xA);
    float* p_tM    = symf(g_tM);
    float* p_tA    = symf(g_tA);
    float* p_gn1   = symf(g_gn1);
    float* p_gn2   = symf(g_gn2);
    float* p_v     = symf(g_v);
    float* p_u     = symf(g_u);
    float* p_xg    = symf(g_xg);
    float* p_y     = symf(g_y);

    // 1) Big GEMM (x = x0 @ W^T + b) with fused max/sum-over-L epilogue
    dim3 grid1(NLT, NC / 128, NB);
    gemm1_maxsum<<<grid1, 256>>>(x0, W, b);
    reduce_maxsum<<<(NB * NC) / 256, 256>>>();

    // 2) Pooled branches: t = pooled @ Wm^T/Wa^T + bias, then GroupNorm
    dim3 gst(NC / 8, NB);
    small_gemm_T<<<gst, 256>>>(p_xmean, Wm, bm, p_tM);
    small_gemm_T<<<gst, 256>>>(p_xA, Wa, ba, p_tA);
    gn_kernel<<<NB, 1024>>>(p_tM, g1w, g1b, p_gn1);
    gn_kernel<<<NB, 1024>>>(p_tA, g2w, g2b, p_gn2);

    // 3) v = (gn1 + gn2-branch) pushed through W1 (reduce over rows), then u = v @ W
    dim3 gsn(NC / 256, NB);
    small_gemm_N<false><<<gsn, 256>>>(p_gn1, W1, p_v);
    small_gemm_N<true ><<<gsn, 256>>>(p_gn2, W1, p_v);
    small_gemm_N<false><<<gsn, 256>>>(p_v, W, p_u);

    // 4) scores s[b,l] = x0 . u  (softmax product ordering == out1+out2 ordering)
    dim3 gdot(NL / 8, NB);
    dot_kernel<<<gdot, 256>>>(x0);

    // 5) top-20 per batch, gather selected x0 rows
    topk_kernel<<<NB, 256>>>();
    gather_kernel<<<NB * KSEL, 256>>>(x0);

    // 6) exact fp32 recompute of the two linears for the 640 selected rows
    dim3 gg2((NB * KSEL) / 64, NC / 64);
    gemm2<<<gg2, 256>>>(p_xg, W, b, p_y);
    gemm2<<<gg2, 256>>>(p_y, W1, b1, out);
}